// round 13
// baseline (speedup 1.0000x reference)
#include <cuda_runtime.h>
#include <cstdint>

// Problem constants (fixed by the reference)
#define B_SZ   16384
#define S_GRID 7
#define CELLS_PER_B   49            // 7*7
#define CH     30
#define N_CELLS (B_SZ * CELLS_PER_B)   // 802816
#define BLOCK  256
#define GRID_N (N_CELLS / BLOCK)       // 3136 exactly
#define WAVE   592                     // 148 SMs x 4 CTAs -> one wave of blocks
#define INP_TOTAL_BYTES ((size_t)B_SZ * CH * CELLS_PER_B * 4)   // 96,337,920 (mult of 128)

#define CELL_PX 64.0f
#define IMG_PX  448.0f

// grid-wide accumulator (zero-initialized at module load; reset by the last
// finishing block -> deterministic across graph replays, no zeroing kernel)
__device__ float        g_acc;
__device__ unsigned int g_done;

__device__ __forceinline__ uint32_t smem_u32(const void* p) {
    uint32_t a;
    asm("{ .reg .u64 t; cvta.to.shared.u64 t, %1; cvt.u32.u64 %0, t; }"
        : "=r"(a) : "l"(p));
    return a;
}

__device__ __forceinline__ float4 decode_box(float p0, float p1, float p2, float p3,
                                             float gx, float gy) {
    float cx = p0 * CELL_PX + gx;
    float cy = p1 * CELL_PX + gy;
    float w  = p2 * IMG_PX;
    float h  = p3 * IMG_PX;
    float4 r;
    r.x = fminf(fmaxf(cx - w * 0.5f, 0.0f), IMG_PX);
    r.y = fminf(fmaxf(cy - h * 0.5f, 0.0f), IMG_PX);
    r.z = fminf(fmaxf(cx + w * 0.5f, 0.0f), IMG_PX);
    r.w = fminf(fmaxf(cy + h * 0.5f, 0.0f), IMG_PX);
    return r;
}

__device__ __forceinline__ float iou_fn(float4 a, float4 b) {
    float l  = fmaxf(a.x, b.x);
    float r  = fminf(a.z, b.z);
    float tt = fmaxf(a.y, b.y);
    float bo = fminf(a.w, b.w);
    bool m = (l < r) && (tt < bo);
    float inter = (r - l) * (bo - tt);
    float uni = (a.z - a.x) * (a.w - a.y) + (b.z - b.x) * (b.w - b.y);
    return m ? inter / (uni - inter) : 0.0f;
}

__global__ __launch_bounds__(BLOCK) void yolo_loss_kernel(
    const float* __restrict__ inp,   // [B, 30, 7, 7]
    const float* __restrict__ tgt,   // [B, 7, 7, 30]  == [N_CELLS, 30]
    float* __restrict__ out)
{
    __shared__ float st[BLOCK * CH];      // target slab: 256 cells x 30 ch = 30720 B
    __shared__ float warp_sums[BLOCK / 32];

    const int n0 = blockIdx.x * BLOCK;

    // ---- L2 prefetch for the tile one wave ahead (fire-and-forget) ----
    if (threadIdx.x == 0) {
        int pb = blockIdx.x + WAVE;
        if (pb < GRID_N) {
            int n0p = pb * BLOCK;
            // target slab: contiguous 30720 B at byte offset n0p*120 (mult of 30720 -> aligned)
            const char* tp = reinterpret_cast<const char*>(tgt) + (size_t)n0p * (CH * 4);
            asm volatile("cp.async.bulk.prefetch.L2.global [%0], %1;"
                         :: "l"(tp), "r"((uint32_t)(BLOCK * CH * 4)) : "memory");
            // input: batch slabs covering cells [n0p, n0p+256), 128-B aligned window
            int b_lo = n0p / CELLS_PER_B;
            int b_hi = (n0p + BLOCK - 1) / CELLS_PER_B;          // inclusive
            size_t beg = (size_t)b_lo * (CH * CELLS_PER_B * 4);
            size_t end = (size_t)(b_hi + 1) * (CH * CELLS_PER_B * 4);
            beg &= ~(size_t)127;                                  // align down 128
            end = (end + 127) & ~(size_t)127;                     // align up 128
            if (end > INP_TOTAL_BYTES) end = INP_TOTAL_BYTES;     // stays 128-aligned
            const char* ip = reinterpret_cast<const char*>(inp) + beg;
            asm volatile("cp.async.bulk.prefetch.L2.global [%0], %1;"
                         :: "l"(ip), "r"((uint32_t)(end - beg)) : "memory");
        }
    }

    // ---- stage target slab via cp.async (no register round-trip) ----
    {
        const float4* tg4 = reinterpret_cast<const float4*>(tgt + (size_t)n0 * CH);
        uint32_t st_base = smem_u32(st);
        #pragma unroll
        for (int k = 0; k < 8; k++) {
            int i = threadIdx.x + k * BLOCK;
            if (i < (BLOCK * CH) / 4) {
                asm volatile("cp.async.ca.shared.global [%0], [%1], 16;\n"
                             :: "r"(st_base + i * 16), "l"(tg4 + i));
            }
        }
        asm volatile("cp.async.commit_group;\n" ::: "memory");
    }

    // ---- issue all 30 input loads while cp.async is in flight ----
    const int n    = n0 + threadIdx.x;
    const int b    = n / CELLS_PER_B;
    const int cell = n - b * CELLS_PER_B;
    const int row  = cell / S_GRID;
    const int col  = cell - row * S_GRID;
    const float gx = (float)col * CELL_PX;
    const float gy = (float)row * CELL_PX;

    // input: channel-major, stride 49 per channel; contiguous across threads
    const float* xb = inp + (size_t)b * (CH * CELLS_PER_B) + cell;
    float x[CH];
    #pragma unroll
    for (int c = 0; c < CH; c++)
        x[c] = __ldg(&xb[c * CELLS_PER_B]);

    asm volatile("cp.async.wait_group 0;\n" ::: "memory");
    __syncthreads();

    const float* t = st + threadIdx.x * CH;

    float4 pb1 = decode_box(x[0], x[1], x[2], x[3], gx, gy);
    float4 pb2 = decode_box(x[5], x[6], x[7], x[8], gx, gy);
    float4 tb1 = decode_box(t[0], t[1], t[2], t[3], gx, gy);
    float4 tb2 = decode_box(t[5], t[6], t[7], t[8], gx, gy);

    float iou1 = iou_fn(pb1, tb1);
    float iou2 = iou_fn(pb2, tb2);
    bool  mask = iou1 < iou2;
    float iou  = mask ? iou2 : iou1;

    float s0 = mask ? x[5] : x[0];
    float s1 = mask ? x[6] : x[1];
    float s2 = mask ? x[7] : x[2];
    float s3 = mask ? x[8] : x[3];
    float s4 = mask ? x[9] : x[4];

    float w = (t[4] == 1.0f) ? 1.0f : 0.0f;

    float d0 = s0 - t[0], d1 = s1 - t[1];
    float coord = d0 * d0 + d1 * d1;
    float e2 = sqrtf(s2) - sqrtf(t[2]);
    float e3 = sqrtf(s3) - sqrtf(t[3]);
    float size = e2 * e2 + e3 * e3;
    float dc = s4 - iou;
    float conf = dc * dc;
    float noobj = s4 * s4;

    float cls = 0.0f;
    #pragma unroll
    for (int c = 10; c < CH; c++) {
        float d = x[c] - t[c];
        cls += d * d;
    }

    float loss = w * (5.0f * coord + 5.0f * size + conf + cls)
               + (1.0f - w) * 0.5f * noobj;

    // ---- block reduction ----
    #pragma unroll
    for (int o = 16; o > 0; o >>= 1)
        loss += __shfl_down_sync(0xFFFFFFFFu, loss, o);

    const int lane = threadIdx.x & 31;
    const int wid  = threadIdx.x >> 5;
    if (lane == 0) warp_sums[wid] = loss;
    __syncthreads();

    if (threadIdx.x == 0) {
        float v = 0.0f;
        #pragma unroll
        for (int i = 0; i < BLOCK / 32; i++) v += warp_sums[i];

        atomicAdd(&g_acc, v);
        __threadfence();
        unsigned int done = atomicAdd(&g_done, 1u);
        if (done == GRID_N - 1) {
            out[0] = g_acc;      // publish result
            g_acc  = 0.0f;       // reset for next graph replay
            g_done = 0u;
        }
    }
}

extern "C" void kernel_launch(void* const* d_in, const int* in_sizes, int n_in,
                              void* d_out, int out_size) {
    const float* inp = (const float*)d_in[0];   // [16384, 30, 7, 7]
    const float* tgt = (const float*)d_in[1];   // [16384, 7, 7, 30]
    float* out = (float*)d_out;                 // scalar

    yolo_loss_kernel<<<GRID_N, BLOCK>>>(inp, tgt, out);
}

// round 14
// speedup vs baseline: 1.1214x; 1.1214x over previous
#include <cuda_runtime.h>
#include <cstdint>

// Problem constants (fixed by the reference)
#define B_SZ   16384
#define S_GRID 7
#define CELLS_PER_B   49            // 7*7
#define CH     30
#define N_CELLS (B_SZ * CELLS_PER_B)   // 802816
#define BLOCK  256
#define GRID_N (N_CELLS / BLOCK)       // 3136 exactly

#define CELL_PX 64.0f
#define IMG_PX  448.0f

// grid-wide accumulator (zero-initialized at module load; reset by the last
// finishing block -> deterministic across graph replays, no zeroing kernel)
__device__ float        g_acc;
__device__ unsigned int g_count;

__device__ __forceinline__ uint32_t smem_u32(const void* p) {
    uint32_t a;
    asm("{ .reg .u64 t; cvta.to.shared.u64 t, %1; cvt.u32.u64 %0, t; }"
        : "=r"(a) : "l"(p));
    return a;
}

__device__ __forceinline__ float4 decode_box(float p0, float p1, float p2, float p3,
                                             float gx, float gy) {
    float cx = p0 * CELL_PX + gx;
    float cy = p1 * CELL_PX + gy;
    float w  = p2 * IMG_PX;
    float h  = p3 * IMG_PX;
    float4 r;
    r.x = fminf(fmaxf(cx - w * 0.5f, 0.0f), IMG_PX);
    r.y = fminf(fmaxf(cy - h * 0.5f, 0.0f), IMG_PX);
    r.z = fminf(fmaxf(cx + w * 0.5f, 0.0f), IMG_PX);
    r.w = fminf(fmaxf(cy + h * 0.5f, 0.0f), IMG_PX);
    return r;
}

__device__ __forceinline__ float iou_fn(float4 a, float4 b) {
    float l  = fmaxf(a.x, b.x);
    float r  = fminf(a.z, b.z);
    float tt = fmaxf(a.y, b.y);
    float bo = fminf(a.w, b.w);
    bool m = (l < r) && (tt < bo);
    float inter = (r - l) * (bo - tt);
    float uni = (a.z - a.x) * (a.w - a.y) + (b.z - b.x) * (b.w - b.y);
    return m ? inter / (uni - inter) : 0.0f;
}

__global__ __launch_bounds__(BLOCK) void yolo_loss_kernel(
    const float* __restrict__ inp,   // [B, 30, 7, 7]
    const float* __restrict__ tgt,   // [B, 7, 7, 30]  == [N_CELLS, 30]
    float* __restrict__ out)
{
    __shared__ float st[BLOCK * CH];      // target slab: 256 cells x 30 ch = 30720 B
    __shared__ float warp_sums[BLOCK / 32];

    const int n0 = blockIdx.x * BLOCK;

    // ---- stage target slab via cp.async (no register round-trip) ----
    // base byte offset = n0*120B, 16B-aligned since n0 % 256 == 0
    {
        const float4* tg4 = reinterpret_cast<const float4*>(tgt + (size_t)n0 * CH);
        uint32_t st_base = smem_u32(st);
        #pragma unroll
        for (int k = 0; k < 8; k++) {
            int i = threadIdx.x + k * BLOCK;
            if (i < (BLOCK * CH) / 4) {
                asm volatile("cp.async.ca.shared.global [%0], [%1], 16;\n"
                             :: "r"(st_base + i * 16), "l"(tg4 + i));
            }
        }
        asm volatile("cp.async.commit_group;\n" ::: "memory");
    }

    // ---- issue all input loads while cp.async is in flight ----
    const int n    = n0 + threadIdx.x;
    const int b    = n / CELLS_PER_B;
    const int cell = n - b * CELLS_PER_B;
    const int row  = cell / S_GRID;
    const int col  = cell - row * S_GRID;
    const float gx = (float)col * CELL_PX;
    const float gy = (float)row * CELL_PX;

    // input: channel-major, stride 49 per channel; contiguous across threads
    const float* xb = inp + (size_t)b * (CH * CELLS_PER_B) + cell;
    float x[CH];
    #pragma unroll
    for (int c = 0; c < CH; c++)
        x[c] = __ldg(&xb[c * CELLS_PER_B]);

    asm volatile("cp.async.wait_group 0;\n" ::: "memory");
    __syncthreads();

    const float* t = st + threadIdx.x * CH;

    float4 pb1 = decode_box(x[0], x[1], x[2], x[3], gx, gy);
    float4 pb2 = decode_box(x[5], x[6], x[7], x[8], gx, gy);
    float4 tb1 = decode_box(t[0], t[1], t[2], t[3], gx, gy);
    float4 tb2 = decode_box(t[5], t[6], t[7], t[8], gx, gy);

    float iou1 = iou_fn(pb1, tb1);
    float iou2 = iou_fn(pb2, tb2);
    bool  mask = iou1 < iou2;
    float iou  = mask ? iou2 : iou1;

    float s0 = mask ? x[5] : x[0];
    float s1 = mask ? x[6] : x[1];
    float s2 = mask ? x[7] : x[2];
    float s3 = mask ? x[8] : x[3];
    float s4 = mask ? x[9] : x[4];

    float w = (t[4] == 1.0f) ? 1.0f : 0.0f;

    float d0 = s0 - t[0], d1 = s1 - t[1];
    float coord = d0 * d0 + d1 * d1;
    float e2 = sqrtf(s2) - sqrtf(t[2]);
    float e3 = sqrtf(s3) - sqrtf(t[3]);
    float size = e2 * e2 + e3 * e3;
    float dc = s4 - iou;
    float conf = dc * dc;
    float noobj = s4 * s4;

    float cls = 0.0f;
    #pragma unroll
    for (int c = 10; c < CH; c++) {
        float d = x[c] - t[c];
        cls += d * d;
    }

    float loss = w * (5.0f * coord + 5.0f * size + conf + cls)
               + (1.0f - w) * 0.5f * noobj;

    // ---- block reduction ----
    #pragma unroll
    for (int o = 16; o > 0; o >>= 1)
        loss += __shfl_down_sync(0xFFFFFFFFu, loss, o);

    const int lane = threadIdx.x & 31;
    const int wid  = threadIdx.x >> 5;
    if (lane == 0) warp_sums[wid] = loss;
    __syncthreads();

    if (threadIdx.x == 0) {
        float v = 0.0f;
        #pragma unroll
        for (int i = 0; i < BLOCK / 32; i++) v += warp_sums[i];

        atomicAdd(&g_acc, v);
        __threadfence();
        unsigned int done = atomicAdd(&g_count, 1u);
        if (done == GRID_N - 1) {
            out[0]  = g_acc;     // publish result
            g_acc   = 0.0f;      // reset for next graph replay
            g_count = 0u;
        }
    }
}

extern "C" void kernel_launch(void* const* d_in, const int* in_sizes, int n_in,
                              void* d_out, int out_size) {
    const float* inp = (const float*)d_in[0];   // [16384, 30, 7, 7]
    const float* tgt = (const float*)d_in[1];   // [16384, 7, 7, 30]
    float* out = (float*)d_out;                 // scalar

    yolo_loss_kernel<<<GRID_N, BLOCK>>>(inp, tgt, out);
}

// round 16
// speedup vs baseline: 1.1979x; 1.0682x over previous
#include <cuda_runtime.h>
#include <cstdint>

// Problem constants (fixed by the reference)
#define B_SZ   16384
#define S_GRID 7
#define CELLS_PER_B   49            // 7*7
#define CH     30
#define N_CELLS (B_SZ * CELLS_PER_B)   // 802816
#define BLOCK  128
#define GRID_N (N_CELLS / BLOCK)       // 6272 exactly
#define SLAB_V4 ((BLOCK * CH) / 4)     // 960 float4 chunks per tile

#define CELL_PX 64.0f
#define IMG_PX  448.0f

// grid-wide accumulator (zero-initialized at module load; reset by the last
// finishing block -> deterministic across graph replays, no zeroing kernel)
__device__ float        g_acc;
__device__ unsigned int g_count;

__device__ __forceinline__ uint32_t smem_u32(const void* p) {
    uint32_t a;
    asm("{ .reg .u64 t; cvta.to.shared.u64 t, %1; cvt.u32.u64 %0, t; }"
        : "=r"(a) : "l"(p));
    return a;
}

__device__ __forceinline__ float4 decode_box(float p0, float p1, float p2, float p3,
                                             float gx, float gy) {
    float cx = p0 * CELL_PX + gx;
    float cy = p1 * CELL_PX + gy;
    float w  = p2 * IMG_PX;
    float h  = p3 * IMG_PX;
    float4 r;
    r.x = fminf(fmaxf(cx - w * 0.5f, 0.0f), IMG_PX);
    r.y = fminf(fmaxf(cy - h * 0.5f, 0.0f), IMG_PX);
    r.z = fminf(fmaxf(cx + w * 0.5f, 0.0f), IMG_PX);
    r.w = fminf(fmaxf(cy + h * 0.5f, 0.0f), IMG_PX);
    return r;
}

__device__ __forceinline__ float iou_fn(float4 a, float4 b) {
    float l  = fmaxf(a.x, b.x);
    float r  = fminf(a.z, b.z);
    float tt = fmaxf(a.y, b.y);
    float bo = fminf(a.w, b.w);
    bool m = (l < r) && (tt < bo);
    float inter = (r - l) * (bo - tt);
    float uni = (a.z - a.x) * (a.w - a.y) + (b.z - b.x) * (b.w - b.y);
    return m ? inter / (uni - inter) : 0.0f;
}

__global__ __launch_bounds__(BLOCK) void yolo_loss_kernel(
    const float* __restrict__ inp,   // [B, 30, 7, 7]
    const float* __restrict__ tgt,   // [B, 7, 7, 30]  == [N_CELLS, 30]
    float* __restrict__ out)
{
    __shared__ float st[BLOCK * CH];      // target slab: 128 cells x 30 ch = 15360 B
    __shared__ float warp_sums[BLOCK / 32];

    const int n0 = blockIdx.x * BLOCK;

    // ---- stage target slab via cp.async (no register round-trip) ----
    // 960 float4 chunks, 8 iterations of 128 threads (last half-iteration guarded)
    {
        const float4* tg4 = reinterpret_cast<const float4*>(tgt + (size_t)n0 * CH);
        uint32_t st_base = smem_u32(st);
        #pragma unroll
        for (int k = 0; k < 8; k++) {
            int i = threadIdx.x + k * BLOCK;
            if (i < SLAB_V4) {
                asm volatile("cp.async.ca.shared.global [%0], [%1], 16;\n"
                             :: "r"(st_base + i * 16), "l"(tg4 + i));
            }
        }
        asm volatile("cp.async.commit_group;\n" ::: "memory");
    }

    // ---- issue all input loads while cp.async is in flight ----
    const int n    = n0 + threadIdx.x;
    const int b    = n / CELLS_PER_B;
    const int cell = n - b * CELLS_PER_B;
    const int row  = cell / S_GRID;
    const int col  = cell - row * S_GRID;
    const float gx = (float)col * CELL_PX;
    const float gy = (float)row * CELL_PX;

    // input: channel-major, stride 49 per channel; contiguous across threads
    const float* xb = inp + (size_t)b * (CH * CELLS_PER_B) + cell;
    float x[CH];
    #pragma unroll
    for (int c = 0; c < CH; c++)
        x[c] = __ldg(&xb[c * CELLS_PER_B]);

    asm volatile("cp.async.wait_group 0;\n" ::: "memory");
    __syncthreads();

    const float* t = st + threadIdx.x * CH;

    float4 pb1 = decode_box(x[0], x[1], x[2], x[3], gx, gy);
    float4 pb2 = decode_box(x[5], x[6], x[7], x[8], gx, gy);
    float4 tb1 = decode_box(t[0], t[1], t[2], t[3], gx, gy);
    float4 tb2 = decode_box(t[5], t[6], t[7], t[8], gx, gy);

    float iou1 = iou_fn(pb1, tb1);
    float iou2 = iou_fn(pb2, tb2);
    bool  mask = iou1 < iou2;
    float iou  = mask ? iou2 : iou1;

    float s0 = mask ? x[5] : x[0];
    float s1 = mask ? x[6] : x[1];
    float s2 = mask ? x[7] : x[2];
    float s3 = mask ? x[8] : x[3];
    float s4 = mask ? x[9] : x[4];

    float w = (t[4] == 1.0f) ? 1.0f : 0.0f;

    float d0 = s0 - t[0], d1 = s1 - t[1];
    float coord = d0 * d0 + d1 * d1;
    float e2 = sqrtf(s2) - sqrtf(t[2]);
    float e3 = sqrtf(s3) - sqrtf(t[3]);
    float size = e2 * e2 + e3 * e3;
    float dc = s4 - iou;
    float conf = dc * dc;
    float noobj = s4 * s4;

    float cls = 0.0f;
    #pragma unroll
    for (int c = 10; c < CH; c++) {
        float d = x[c] - t[c];
        cls += d * d;
    }

    float loss = w * (5.0f * coord + 5.0f * size + conf + cls)
               + (1.0f - w) * 0.5f * noobj;

    // ---- block reduction ----
    #pragma unroll
    for (int o = 16; o > 0; o >>= 1)
        loss += __shfl_down_sync(0xFFFFFFFFu, loss, o);

    const int lane = threadIdx.x & 31;
    const int wid  = threadIdx.x >> 5;
    if (lane == 0) warp_sums[wid] = loss;
    __syncthreads();

    if (threadIdx.x == 0) {
        float v = 0.0f;
        #pragma unroll
        for (int i = 0; i < BLOCK / 32; i++) v += warp_sums[i];

        atomicAdd(&g_acc, v);
        __threadfence();
        unsigned int done = atomicAdd(&g_count, 1u);
        if (done == GRID_N - 1) {
            out[0]  = g_acc;     // publish result
            g_acc   = 0.0f;      // reset for next graph replay
            g_count = 0u;
        }
    }
}

extern "C" void kernel_launch(void* const* d_in, const int* in_sizes, int n_in,
                              void* d_out, int out_size) {
    const float* inp = (const float*)d_in[0];   // [16384, 30, 7, 7]
    const float* tgt = (const float*)d_in[1];   // [16384, 7, 7, 30]
    float* out = (float*)d_out;                 // scalar

    yolo_loss_kernel<<<GRID_N, BLOCK>>>(inp, tgt, out);
}